// round 13
// baseline (speedup 1.0000x reference)
#include <cuda_runtime.h>
#include <cuda_bf16.h>
#include <cuda_fp16.h>

#define NNODES 100000
#define NEDGES 1600000
#define DIM 64
#define NEG_SLOPE 0.2f
#define BN_EPS 1e-5f
#define SCAN_BS 1024
#define FULLM 0xffffffffu

// Packed dual-fp32 FMA (sm_103a FFMA2) — PTX-only, full fp32 precision.
#define FMA2(D, A, B, C) \
    asm("fma.rn.f32x2 %0, %1, %2, %3;" : "=l"(D) : "l"(A), "l"(B), "l"(C))
#define PACKF2(D, LO, HI) \
    asm("mov.b64 %0, {%1, %2};" : "=l"(D) : "f"(LO), "f"(HI))
#define UNPACKF2(LO, HI, S) \
    asm("mov.b64 {%0, %1}, %2;" : "=f"(LO), "=f"(HI) : "l"(S))

// ---------------- scratch -----------------------------------------------
__device__ __half g_featH[NNODES * DIM];  // projected features, fp16 rows (128B)
__device__ float  g_acc [NNODES * DIM];   // layer output (pre-BN), fp32
__device__ float  g_el  [NNODES];
__device__ float  g_er  [NNODES];
__device__ int    g_deg [NNODES];         // zero-init; self-restored each run
__device__ int    g_rowptr[NNODES + 1];
__device__ int    g_off [NNODES];
__device__ int    g_srcsorted[NEDGES];
__device__ int    g_bsum[256];
__device__ double g_bnsum2[3][DIM];
__device__ double g_bnsq2 [3][DIM];

// Side stream + events (created pre-main, no device memory).
struct AuxStreams {
    cudaStream_t s2;
    cudaEvent_t  e0, e1;
    AuxStreams() {
        cudaStreamCreateWithFlags(&s2, cudaStreamNonBlocking);
        cudaEventCreateWithFlags(&e0, cudaEventDisableTiming);
        cudaEventCreateWithFlags(&e1, cudaEventDisableTiming);
    }
};
static AuxStreams g_aux;

// ---------------- CSR build (R11 form — atomic/sector-traffic bound) -----
__global__ void k_hist(const int* __restrict__ dst, int E) {
    int e = blockIdx.x * blockDim.x + threadIdx.x;
    if (e < E) atomicAdd(&g_deg[dst[e]], 1);
}
// scan1 re-zeroes g_deg after reading (zero at static init for run 1).
__global__ void k_scan1(int n) {
    __shared__ int wsum[32];
    int t = threadIdx.x, lane = t & 31, w = t >> 5;
    int idx = blockIdx.x * SCAN_BS + t;
    int val = (idx < n) ? g_deg[idx] : 0;
    if (idx < n) g_deg[idx] = 0;
    int x = val;
    #pragma unroll
    for (int off = 1; off < 32; off <<= 1) {
        int y = __shfl_up_sync(FULLM, x, off);
        if (lane >= off) x += y;
    }
    if (lane == 31) wsum[w] = x;
    __syncthreads();
    if (w == 0) {
        int y = wsum[lane];
        int z = y;
        #pragma unroll
        for (int off = 1; off < 32; off <<= 1) {
            int u = __shfl_up_sync(FULLM, z, off);
            if (lane >= off) z += u;
        }
        wsum[lane] = z - y;
    }
    __syncthreads();
    int incl = x + wsum[w];
    if (idx < n) g_rowptr[idx] = incl - val;
    if (t == SCAN_BS - 1) g_bsum[blockIdx.x] = incl;
}
// scan2+scan3 merged: every block redundantly scans the <=128 block sums,
// then applies the offset to its slice of rowptr.
__global__ void k_scan23(int nb, int n) {
    __shared__ int sboff[129];
    int t = threadIdx.x;
    if (t == 0) {
        int a = 0;
        for (int i = 0; i < nb; i++) { sboff[i] = a; a += g_bsum[i]; }
        sboff[nb] = a;                      // total = E
    }
    __syncthreads();
    int i = blockIdx.x * blockDim.x + t;
    if (i < n) {
        int v = g_rowptr[i] + sboff[i / SCAN_BS];
        g_rowptr[i] = v;
        g_off[i] = v;
    }
    if (i == n) g_rowptr[n] = sboff[nb];
}
// place also zeroes the BN stat slots (block 0) — strictly before any k_agg.
__global__ void k_place(const int* __restrict__ src,
                        const int* __restrict__ dst, int E) {
    if (blockIdx.x == 0 && threadIdx.x < 192) {
        ((double*)g_bnsum2)[threadIdx.x] = 0.0;
        ((double*)g_bnsq2)[threadIdx.x] = 0.0;
    }
    int e = blockIdx.x * blockDim.x + threadIdx.x;
    if (e < E) {
        int pos = atomicAdd(&g_off[dst[e]], 1);
        g_srcsorted[pos] = src[e];
    }
}

// ---------------- K1: feat = h @ W via FFMA2 with pre-duplicated weights --
// WdA[k][cg] = (wx,wx,wy,wy), WdB[k][cg] = (wz,wz,ww,ww): 16B stride per cg
// -> conflict-free LDS.128, feeds FMA2 with ZERO weight packs in the loop.
// Static smem = 16 + 16 + 16 = 48KB exactly; the BN scale/shift scratch
// lives in WdA[0..127] before the weight fill (sync-separated).
__global__ void k_gemm(const float* __restrict__ hin_ext, int layer,
                       const float* __restrict__ W,
                       const float* __restrict__ al,
                       const float* __restrict__ ar,
                       const float* __restrict__ gmaP,
                       const float* __restrict__ betaP,
                       int n) {
    __shared__ float WdA[DIM * 16 * 4];   // 16KB
    __shared__ float WdB[DIM * 16 * 4];   // 16KB
    __shared__ float hs [64 * DIM];       // 16KB

    int t = threadIdx.x;
    int row0 = blockIdx.x * 64;
    int nrows = n - row0; if (nrows > 64) nrows = 64;

    if (layer > 0) {
        // scale/shift scratch in WdA[0..63] / WdA[64..127]
        if (t < DIM) {
            double inv_n = 1.0 / (double)n;
            double mu  = g_bnsum2[layer - 1][t] * inv_n;
            double var = g_bnsq2[layer - 1][t] * inv_n - mu * mu;
            float rs = rsqrtf((float)var + BN_EPS);
            float sc = rs * gmaP[t];
            WdA[t] = sc;
            WdA[64 + t] = betaP[t] - (float)mu * sc;
        }
        __syncthreads();
        for (int i = t; i < nrows * (DIM / 4); i += 256) {
            float4 a = ((const float4*)(g_acc + (size_t)row0 * DIM))[i];
            int c = (i & 15) * 4;
            float4 v;
            v.x = a.x * WdA[c + 0] + WdA[64 + c + 0];
            v.y = a.y * WdA[c + 1] + WdA[64 + c + 1];
            v.z = a.z * WdA[c + 2] + WdA[64 + c + 2];
            v.w = a.w * WdA[c + 3] + WdA[64 + c + 3];
            v.x = v.x > 0.f ? v.x : (__expf(v.x) - 1.f);
            v.y = v.y > 0.f ? v.y : (__expf(v.y) - 1.f);
            v.z = v.z > 0.f ? v.z : (__expf(v.z) - 1.f);
            v.w = v.w > 0.f ? v.w : (__expf(v.w) - 1.f);
            ((float4*)hs)[i] = v;
        }
        __syncthreads();   // staging done before WdA is overwritten
    } else {
        for (int i = t; i < nrows * (DIM / 4); i += 256)
            ((float4*)hs)[i] = ((const float4*)(hin_ext + (size_t)row0 * DIM))[i];
    }

    // fill duplicated-weight tables (overwrites the scratch region)
    for (int i = t; i < DIM * 16; i += 256) {
        float4 w = ((const float4*)W)[i];           // i = k*16 + cg
        ((float4*)WdA)[i] = make_float4(w.x, w.x, w.y, w.y);
        ((float4*)WdB)[i] = make_float4(w.z, w.z, w.w, w.w);
    }
    __syncthreads();

    int cg = t & 15, rg = t >> 4;
    int r0 = rg * 4;

    unsigned long long accP[2][4];
    #pragma unroll
    for (int rp = 0; rp < 2; rp++)
        #pragma unroll
        for (int c = 0; c < 4; c++) accP[rp][c] = 0ULL;

    #pragma unroll
    for (int k = 0; k < DIM; k += 4) {
        float4 hA = *(const float4*)(hs + (r0 + 0) * DIM + k);
        float4 hB = *(const float4*)(hs + (r0 + 1) * DIM + k);
        float4 hC = *(const float4*)(hs + (r0 + 2) * DIM + k);
        float4 hD = *(const float4*)(hs + (r0 + 3) * DIM + k);
        const float* pA = &hA.x; const float* pB = &hB.x;
        const float* pC = &hC.x; const float* pD = &hD.x;
        #pragma unroll
        for (int kk = 0; kk < 4; kk++) {
            ulonglong2 w01 = *(const ulonglong2*)(WdA + ((k + kk) * 16 + cg) * 4);
            ulonglong2 w23 = *(const ulonglong2*)(WdB + ((k + kk) * 16 + cg) * 4);
            unsigned long long h01, h23;
            PACKF2(h01, pA[kk], pB[kk]);
            PACKF2(h23, pC[kk], pD[kk]);
            FMA2(accP[0][0], h01, w01.x, accP[0][0]);
            FMA2(accP[0][1], h01, w01.y, accP[0][1]);
            FMA2(accP[0][2], h01, w23.x, accP[0][2]);
            FMA2(accP[0][3], h01, w23.y, accP[0][3]);
            FMA2(accP[1][0], h23, w01.x, accP[1][0]);
            FMA2(accP[1][1], h23, w01.y, accP[1][1]);
            FMA2(accP[1][2], h23, w23.x, accP[1][2]);
            FMA2(accP[1][3], h23, w23.y, accP[1][3]);
        }
    }

    float accf[4][4];
    #pragma unroll
    for (int rp = 0; rp < 2; rp++)
        #pragma unroll
        for (int c = 0; c < 4; c++)
            UNPACKF2(accf[2 * rp][c], accf[2 * rp + 1][c], accP[rp][c]);

    float4 alv = ((const float4*)al)[cg];
    float4 arv = ((const float4*)ar)[cg];
    #pragma unroll
    for (int r = 0; r < 4; r++) {
        int row = row0 + r0 + r;
        float ax = accf[r][0], ay = accf[r][1], az = accf[r][2], aw = accf[r][3];
        float pl = ax * alv.x + ay * alv.y + az * alv.z + aw * alv.w;
        float pr = ax * arv.x + ay * arv.y + az * arv.z + aw * arv.w;
        #pragma unroll
        for (int off = 8; off > 0; off >>= 1) {
            pl += __shfl_xor_sync(FULLM, pl, off);
            pr += __shfl_xor_sync(FULLM, pr, off);
        }
        if (row < n) {
            __half2 h01 = __floats2half2_rn(ax, ay);
            __half2 h23 = __floats2half2_rn(az, aw);
            uint2 u;
            u.x = *(unsigned int*)&h01;
            u.y = *(unsigned int*)&h23;
            *(uint2*)(g_featH + (size_t)row * DIM + cg * 4) = u;
            if (cg == 0) { g_el[row] = pl; g_er[row] = pr; }
        }
    }
}

// ---------------- K2: fused softmax + aggregation + BN stats -------------
// Warp = four 8-lane quarters; each LDG.128 gathers a different edge's
// 128B fp16 feature row per quarter (4 edges/instruction). Software
// pipelined across the 8 dsts per warp: next dst's srcsorted+el loads
// issue BEFORE the current dst's quad gathers (hides the two dependent
// ~234cy L2 hops). Softmax sum reduced AFTER the quads.
#define QUAD_LOAD(KOFF)                                                   \
    { int   sk = __shfl_sync(FULLM, s,  k + (KOFF) + q);                  \
      float ck = __shfl_sync(FULLM, ex, k + (KOFF) + q);                  \
      uint4 f = fpH[(size_t)sk * 8 + ql];                                 \
      float2 v0 = __half22float2(*(__half2*)&f.x);                        \
      float2 v1 = __half22float2(*(__half2*)&f.y);                        \
      float2 v2 = __half22float2(*(__half2*)&f.z);                        \
      float2 v3 = __half22float2(*(__half2*)&f.w);                        \
      a[0] += ck * v0.x; a[1] += ck * v0.y;                               \
      a[2] += ck * v1.x; a[3] += ck * v1.y;                               \
      a[4] += ck * v2.x; a[5] += ck * v2.y;                               \
      a[6] += ck * v3.x; a[7] += ck * v3.y; }

#define QUAD_LADDER(CNT)                                                  \
    { int k = 0;                                                          \
      for (; k + 16 <= (CNT); k += 16) {                                  \
          QUAD_LOAD(0) QUAD_LOAD(4) QUAD_LOAD(8) QUAD_LOAD(12)            \
      }                                                                   \
      if (k + 8 <= (CNT)) { QUAD_LOAD(0) QUAD_LOAD(4) k += 8; }           \
      if (k + 4 <= (CNT)) { QUAD_LOAD(0) k += 4; }                        \
      if (k < (CNT)) QUAD_LOAD(0) }

__global__ void k_agg(int n, int layer) {
    __shared__ float s_sum[DIM];
    __shared__ float s_sq [DIM];
    int t = threadIdx.x;
    int lane = t & 31;
    int wid = t >> 5;
    int q  = lane >> 3;
    int ql = lane & 7;
    if (t < DIM) { s_sum[t] = 0.f; s_sq[t] = 0.f; }
    __syncthreads();

    const uint4* fpH = (const uint4*)g_featH;
    float bn1[8], bn2[8];
    #pragma unroll
    for (int j = 0; j < 8; j++) { bn1[j] = 0.f; bn2[j] = 0.f; }

    int d_base = blockIdx.x * 64 + wid * 8;
    int idx = d_base + lane; if (idx > n) idx = n;
    int rp = (lane < 9) ? g_rowptr[idx] : 0;
    float erv = (lane < 8 && d_base + lane < n) ? g_er[d_base + lane] : 0.f;

    // prefetch dst 0's first chunk (srcsorted + el)
    int sP = 0; float elP = 0.f;
    if (d_base < n) {
        int rs0 = __shfl_sync(FULLM, rp, 0);
        int re0 = __shfl_sync(FULLM, rp, 1);
        int c0 = re0 - rs0; if (c0 > 32) c0 = 32;
        if (lane < c0) {
            sP = g_srcsorted[rs0 + lane];
            elP = g_el[sP];
        }
    }

    #pragma unroll 1
    for (int i = 0; i < 8; i++) {
        int d = d_base + i;
        if (d >= n) break;
        int rsC = __shfl_sync(FULLM, rp, i);
        int reC = __shfl_sync(FULLM, rp, i + 1);
        int cnt = reC - rsC; if (cnt > 32) cnt = 32;
        float er_d = __shfl_sync(FULLM, erv, i);

        // attention for current dst from prefetched operands
        int s = sP;
        float x = elP + er_d;
        x = x > 0.f ? x : NEG_SLOPE * x;
        float ex = (lane < cnt) ? __expf(x) : 0.f;
        float sum = ex;

        // issue next dst's loads NOW (hidden behind the quads below)
        sP = 0; elP = 0.f;
        if (i < 7 && d + 1 < n) {
            int rsN = reC;
            int reN = __shfl_sync(FULLM, rp, i + 2);
            int cntN = reN - rsN; if (cntN > 32) cntN = 32;
            if (lane < cntN) {
                sP = g_srcsorted[rsN + lane];
                elP = g_el[sP];
            }
        }

        float a[8];
        #pragma unroll
        for (int j = 0; j < 8; j++) a[j] = 0.f;

        // chunk 0 quads (uses s/ex)
        QUAD_LADDER(cnt)

        // extra chunks (degree > 32), serial fallback
        for (int base = rsC + 32; base < reC; base += 32) {
            int cnt2 = reC - base; if (cnt2 > 32) cnt2 = 32;
            int s2 = 0; float ex2 = 0.f;
            if (lane < cnt2) {
                s2 = g_srcsorted[base + lane];
                float x2 = g_el[s2] + er_d;
                x2 = x2 > 0.f ? x2 : NEG_SLOPE * x2;
                ex2 = __expf(x2);
            }
            sum += ex2;
            {
                int s = s2; float ex = ex2;
                QUAD_LADDER(cnt2)
            }
        }

        // softmax denominator (after quads — off the critical path)
        #pragma unroll
        for (int off = 16; off > 0; off >>= 1)
            sum += __shfl_xor_sync(FULLM, sum, off);
        float inv = sum > 0.f ? 1.f / sum : 0.f;

        #pragma unroll
        for (int j = 0; j < 8; j++) {
            a[j] += __shfl_xor_sync(FULLM, a[j], 8);
            a[j] += __shfl_xor_sync(FULLM, a[j], 16);
            a[j] *= inv;
        }

        if (q == 0) {
            float4 lo = make_float4(a[0], a[1], a[2], a[3]);
            float4 hi = make_float4(a[4], a[5], a[6], a[7]);
            ((float4*)g_acc)[(size_t)d * 16 + ql * 2 + 0] = lo;
            ((float4*)g_acc)[(size_t)d * 16 + ql * 2 + 1] = hi;
            #pragma unroll
            for (int j = 0; j < 8; j++) {
                bn1[j] += a[j];
                bn2[j] += a[j] * a[j];
            }
        }
    }

    if (q == 0) {
        #pragma unroll
        for (int j = 0; j < 8; j++) {
            atomicAdd(&s_sum[ql * 8 + j], bn1[j]);
            atomicAdd(&s_sq [ql * 8 + j], bn2[j]);
        }
    }
    __syncthreads();
    if (t < DIM) {
        atomicAdd(&g_bnsum2[layer][t], (double)s_sum[t]);
        atomicAdd(&g_bnsq2 [layer][t], (double)s_sq [t]);
    }
}

// ---------------- K3: final BN apply -------------------------------------
__global__ void k_bnapply(float* __restrict__ out,
                          const float* __restrict__ gma,
                          const float* __restrict__ beta,
                          int n, int total4) {
    __shared__ float scs[DIM], shs[DIM];
    int t = threadIdx.x;
    if (t < DIM) {
        double inv_n = 1.0 / (double)n;
        double mu  = g_bnsum2[2][t] * inv_n;
        double var = g_bnsq2[2][t] * inv_n - mu * mu;
        float rs = rsqrtf((float)var + BN_EPS);
        float sc = rs * gma[t];
        scs[t] = sc;
        shs[t] = beta[t] - (float)mu * sc;
    }
    __syncthreads();
    int idx4 = blockIdx.x * blockDim.x + t;
    if (idx4 >= total4) return;
    int c = (idx4 & 15) * 4;
    float4 a = ((const float4*)g_acc)[idx4];
    float4 v;
    v.x = a.x * scs[c + 0] + shs[c + 0];
    v.y = a.y * scs[c + 1] + shs[c + 1];
    v.z = a.z * scs[c + 2] + shs[c + 2];
    v.w = a.w * scs[c + 3] + shs[c + 3];
    ((float4*)out)[idx4] = v;
}

// ---------------- host ---------------------------------------------------
extern "C" void kernel_launch(void* const* d_in, const int* in_sizes, int n_in,
                              void* d_out, int out_size) {
    const float* node_w = (const float*)d_in[0];
    const int*   src    = (const int*)d_in[2];
    const int*   dst    = (const int*)d_in[3];
    int n = in_sizes[0] / DIM;
    int E = in_sizes[2];
    float* out = (float*)d_out;

    // Fork: CSR build on side stream, layer-0 GEMM on main stream.
    cudaEventRecord(g_aux.e0, 0);
    cudaStreamWaitEvent(g_aux.s2, g_aux.e0, 0);

    int nb = (n + SCAN_BS - 1) / SCAN_BS;
    k_hist  <<<(E + 255) / 256, 256, 0, g_aux.s2>>>(dst, E);
    k_scan1 <<<nb, SCAN_BS, 0, g_aux.s2>>>(n);
    k_scan23<<<(n + 256) / 256, 256, 0, g_aux.s2>>>(nb, n);
    k_place <<<(E + 255) / 256, 256, 0, g_aux.s2>>>(src, dst, E);
    cudaEventRecord(g_aux.e1, g_aux.s2);

    for (int layer = 0; layer < 3; layer++) {
        const float* W    = (const float*)d_in[4 + layer * 6 + 0];
        const float* al   = (const float*)d_in[4 + layer * 6 + 1];
        const float* ar   = (const float*)d_in[4 + layer * 6 + 2];
        const float* gmaP  = layer > 0 ? (const float*)d_in[4 + (layer - 1) * 6 + 4] : nullptr;
        const float* betaP = layer > 0 ? (const float*)d_in[4 + (layer - 1) * 6 + 5] : nullptr;

        k_gemm<<<(n + 63) / 64, 256>>>(layer == 0 ? node_w : nullptr,
                                       layer, W, al, ar, gmaP, betaP, n);
        if (layer == 0) cudaStreamWaitEvent(0, g_aux.e1, 0);  // CSR ready
        k_agg<<<(n + 63) / 64, 256>>>(n, layer);
    }
    const float* gma3  = (const float*)d_in[4 + 2 * 6 + 4];
    const float* beta3 = (const float*)d_in[4 + 2 * 6 + 5];
    int total4 = n * DIM / 4;
    k_bnapply<<<(total4 + 255) / 256, 256>>>(out, gma3, beta3, n, total4);
}

// round 14
// speedup vs baseline: 1.0878x; 1.0878x over previous
#include <cuda_runtime.h>
#include <cuda_bf16.h>
#include <cuda_fp16.h>

#define NNODES 100000
#define NEDGES 1600000
#define DIM 64
#define NEG_SLOPE 0.2f
#define BN_EPS 1e-5f
#define SCAN_BS 1024
#define FULLM 0xffffffffu

// Packed dual-fp32 FMA (sm_103a FFMA2) — PTX-only, full fp32 precision.
#define FMA2(D, A, B, C) \
    asm("fma.rn.f32x2 %0, %1, %2, %3;" : "=l"(D) : "l"(A), "l"(B), "l"(C))
#define PACKF2(D, LO, HI) \
    asm("mov.b64 %0, {%1, %2};" : "=l"(D) : "f"(LO), "f"(HI))
#define UNPACKF2(LO, HI, S) \
    asm("mov.b64 {%0, %1}, %2;" : "=f"(LO), "=f"(HI) : "l"(S))

// ---------------- scratch -----------------------------------------------
__device__ __half g_featH[NNODES * DIM];  // projected features, fp16 rows (128B)
__device__ float  g_acc [NNODES * DIM];   // layer output (pre-BN), fp32
__device__ float  g_el  [NNODES];
__device__ float  g_er  [NNODES];
__device__ int    g_deg [NNODES];         // zero-init; self-restored each run
__device__ int    g_rowptr[NNODES + 1];
__device__ int    g_off [NNODES];
__device__ int    g_srcsorted[NEDGES];
__device__ int    g_bsum[256];
__device__ double g_bnsum2[3][DIM];
__device__ double g_bnsq2 [3][DIM];

// Side stream + events (created pre-main, no device memory).
struct AuxStreams {
    cudaStream_t s2;
    cudaEvent_t  e0, e1;
    AuxStreams() {
        cudaStreamCreateWithFlags(&s2, cudaStreamNonBlocking);
        cudaEventCreateWithFlags(&e0, cudaEventDisableTiming);
        cudaEventCreateWithFlags(&e1, cudaEventDisableTiming);
    }
};
static AuxStreams g_aux;

// ---------------- CSR build ----------------------------------------------
__global__ void k_hist(const int* __restrict__ dst, int E) {
    int e = blockIdx.x * blockDim.x + threadIdx.x;
    if (e < E) atomicAdd(&g_deg[dst[e]], 1);
}
// scan1 re-zeroes g_deg after reading (zero at static init for run 1).
__global__ void k_scan1(int n) {
    __shared__ int wsum[32];
    int t = threadIdx.x, lane = t & 31, w = t >> 5;
    int idx = blockIdx.x * SCAN_BS + t;
    int val = (idx < n) ? g_deg[idx] : 0;
    if (idx < n) g_deg[idx] = 0;
    int x = val;
    #pragma unroll
    for (int off = 1; off < 32; off <<= 1) {
        int y = __shfl_up_sync(FULLM, x, off);
        if (lane >= off) x += y;
    }
    if (lane == 31) wsum[w] = x;
    __syncthreads();
    if (w == 0) {
        int y = wsum[lane];
        int z = y;
        #pragma unroll
        for (int off = 1; off < 32; off <<= 1) {
            int u = __shfl_up_sync(FULLM, z, off);
            if (lane >= off) z += u;
        }
        wsum[lane] = z - y;
    }
    __syncthreads();
    int incl = x + wsum[w];
    if (idx < n) g_rowptr[idx] = incl - val;
    if (t == SCAN_BS - 1) g_bsum[blockIdx.x] = incl;
}
// scan2+scan3 merged: every block scans the <=128 block sums IN PARALLEL
// (128-thread shfl scan — replaces the serial thread-0 accumulate chain),
// then applies the offset to its slice of rowptr.
__global__ void k_scan23(int nb, int n) {
    __shared__ int sboff[130];
    __shared__ int wsum[4];
    int t = threadIdx.x;
    int lane = t & 31, w = t >> 5;
    int x = 0, val = 0;
    if (t < 128) {
        val = (t < nb) ? g_bsum[t] : 0;
        x = val;
        #pragma unroll
        for (int off = 1; off < 32; off <<= 1) {
            int y = __shfl_up_sync(FULLM, x, off);
            if (lane >= off) x += y;
        }
        if (lane == 31) wsum[w] = x;
    }
    __syncthreads();
    if (t < 128) {
        int add = 0;
        #pragma unroll
        for (int i = 0; i < 4; i++) if (i < w) add += wsum[i];
        int incl = x + add;
        if (t < nb) sboff[t] = incl - val;       // exclusive prefix
        if (t == nb - 1) sboff[nb] = incl;       // total = E
    }
    __syncthreads();
    int i = blockIdx.x * blockDim.x + t;
    if (i < n) {
        int v = g_rowptr[i] + sboff[i / SCAN_BS];
        g_rowptr[i] = v;
        g_off[i] = v;
    }
    if (i == n) g_rowptr[n] = sboff[nb];
}
// place also zeroes the BN stat slots (block 0) — strictly before any k_agg.
__global__ void k_place(const int* __restrict__ src,
                        const int* __restrict__ dst, int E) {
    if (blockIdx.x == 0 && threadIdx.x < 192) {
        ((double*)g_bnsum2)[threadIdx.x] = 0.0;
        ((double*)g_bnsq2)[threadIdx.x] = 0.0;
    }
    int e = blockIdx.x * blockDim.x + threadIdx.x;
    if (e < E) {
        int pos = atomicAdd(&g_off[dst[e]], 1);
        g_srcsorted[pos] = src[e];
    }
}

// ---------------- K1: feat = h @ W via packed f32x2 FMA ------------------
__global__ void k_gemm(const float* __restrict__ hin_ext, int layer,
                       const float* __restrict__ W,
                       const float* __restrict__ al,
                       const float* __restrict__ ar,
                       const float* __restrict__ gmaP,
                       const float* __restrict__ betaP,
                       int n) {
    __shared__ float Ws[DIM * DIM];
    __shared__ float hs[64 * DIM];
    __shared__ float als[DIM], ars[DIM], scs[DIM], shs[DIM];

    int t = threadIdx.x;
    int row0 = blockIdx.x * 64;

    for (int i = t; i < DIM * DIM / 4; i += 256)
        ((float4*)Ws)[i] = ((const float4*)W)[i];
    if (t < DIM) {
        als[t] = al[t]; ars[t] = ar[t];
        if (layer > 0) {
            double inv_n = 1.0 / (double)n;
            double mu  = g_bnsum2[layer - 1][t] * inv_n;
            double var = g_bnsq2[layer - 1][t] * inv_n - mu * mu;
            float rs = rsqrtf((float)var + BN_EPS);
            float sc = rs * gmaP[t];
            scs[t] = sc;
            shs[t] = betaP[t] - (float)mu * sc;
        }
    }
    __syncthreads();

    int nrows = n - row0; if (nrows > 64) nrows = 64;
    if (layer > 0) {
        for (int i = t; i < nrows * (DIM / 4); i += 256) {
            float4 a = ((const float4*)(g_acc + (size_t)row0 * DIM))[i];
            int c = (i & 15) * 4;
            float4 v;
            v.x = a.x * scs[c + 0] + shs[c + 0];
            v.y = a.y * scs[c + 1] + shs[c + 1];
            v.z = a.z * scs[c + 2] + shs[c + 2];
            v.w = a.w * scs[c + 3] + shs[c + 3];
            v.x = v.x > 0.f ? v.x : (__expf(v.x) - 1.f);
            v.y = v.y > 0.f ? v.y : (__expf(v.y) - 1.f);
            v.z = v.z > 0.f ? v.z : (__expf(v.z) - 1.f);
            v.w = v.w > 0.f ? v.w : (__expf(v.w) - 1.f);
            ((float4*)hs)[i] = v;
        }
    } else {
        for (int i = t; i < nrows * (DIM / 4); i += 256)
            ((float4*)hs)[i] = ((const float4*)(hin_ext + (size_t)row0 * DIM))[i];
    }
    __syncthreads();

    int cg = t & 15, rg = t >> 4;
    int r0 = rg * 4;

    unsigned long long accP[2][4];
    #pragma unroll
    for (int rp = 0; rp < 2; rp++)
        #pragma unroll
        for (int c = 0; c < 4; c++) accP[rp][c] = 0ULL;

    const float4* Ws4 = (const float4*)Ws;
    #pragma unroll
    for (int k = 0; k < DIM; k += 4) {
        float4 wv[4];
        wv[0] = Ws4[(k + 0) * 16 + cg];
        wv[1] = Ws4[(k + 1) * 16 + cg];
        wv[2] = Ws4[(k + 2) * 16 + cg];
        wv[3] = Ws4[(k + 3) * 16 + cg];
        float4 hA = *(const float4*)(hs + (r0 + 0) * DIM + k);
        float4 hB = *(const float4*)(hs + (r0 + 1) * DIM + k);
        float4 hC = *(const float4*)(hs + (r0 + 2) * DIM + k);
        float4 hD = *(const float4*)(hs + (r0 + 3) * DIM + k);
        const float* pA = &hA.x; const float* pB = &hB.x;
        const float* pC = &hC.x; const float* pD = &hD.x;
        #pragma unroll
        for (int kk = 0; kk < 4; kk++) {
            unsigned long long h01, h23, wxx, wyy, wzz, www;
            PACKF2(h01, pA[kk], pB[kk]);
            PACKF2(h23, pC[kk], pD[kk]);
            PACKF2(wxx, wv[kk].x, wv[kk].x);
            PACKF2(wyy, wv[kk].y, wv[kk].y);
            PACKF2(wzz, wv[kk].z, wv[kk].z);
            PACKF2(www, wv[kk].w, wv[kk].w);
            FMA2(accP[0][0], h01, wxx, accP[0][0]);
            FMA2(accP[0][1], h01, wyy, accP[0][1]);
            FMA2(accP[0][2], h01, wzz, accP[0][2]);
            FMA2(accP[0][3], h01, www, accP[0][3]);
            FMA2(accP[1][0], h23, wxx, accP[1][0]);
            FMA2(accP[1][1], h23, wyy, accP[1][1]);
            FMA2(accP[1][2], h23, wzz, accP[1][2]);
            FMA2(accP[1][3], h23, www, accP[1][3]);
        }
    }

    float accf[4][4];
    #pragma unroll
    for (int rp = 0; rp < 2; rp++)
        #pragma unroll
        for (int c = 0; c < 4; c++)
            UNPACKF2(accf[2 * rp][c], accf[2 * rp + 1][c], accP[rp][c]);

    float4 alv = ((float4*)als)[cg];
    float4 arv = ((float4*)ars)[cg];
    #pragma unroll
    for (int r = 0; r < 4; r++) {
        int row = row0 + r0 + r;
        float ax = accf[r][0], ay = accf[r][1], az = accf[r][2], aw = accf[r][3];
        float pl = ax * alv.x + ay * alv.y + az * alv.z + aw * alv.w;
        float pr = ax * arv.x + ay * arv.y + az * arv.z + aw * arv.w;
        #pragma unroll
        for (int off = 8; off > 0; off >>= 1) {
            pl += __shfl_xor_sync(FULLM, pl, off);
            pr += __shfl_xor_sync(FULLM, pr, off);
        }
        if (row < n) {
            __half2 h01 = __floats2half2_rn(ax, ay);
            __half2 h23 = __floats2half2_rn(az, aw);
            uint2 u;
            u.x = *(unsigned int*)&h01;
            u.y = *(unsigned int*)&h23;
            *(uint2*)(g_featH + (size_t)row * DIM + cg * 4) = u;
            if (cg == 0) { g_el[row] = pl; g_er[row] = pr; }
        }
    }
}

// ---------------- K2: fused softmax + aggregation + BN stats -------------
// Warp = four 8-lane quarters; each LDG.128 gathers a different edge's
// 128B fp16 feature row per quarter (4 edges/instruction). Software
// pipelined across the 8 dsts per warp: next dst's srcsorted+el loads
// issue BEFORE the current dst's quad gathers (hides the two dependent
// ~234cy L2 hops). Softmax sum reduced AFTER the quads.
#define QUAD_LOAD(KOFF)                                                   \
    { int   sk = __shfl_sync(FULLM, s,  k + (KOFF) + q);                  \
      float ck = __shfl_sync(FULLM, ex, k + (KOFF) + q);                  \
      uint4 f = fpH[(size_t)sk * 8 + ql];                                 \
      float2 v0 = __half22float2(*(__half2*)&f.x);                        \
      float2 v1 = __half22float2(*(__half2*)&f.y);                        \
      float2 v2 = __half22float2(*(__half2*)&f.z);                        \
      float2 v3 = __half22float2(*(__half2*)&f.w);                        \
      a[0] += ck * v0.x; a[1] += ck * v0.y;                               \
      a[2] += ck * v1.x; a[3] += ck * v1.y;                               \
      a[4] += ck * v2.x; a[5] += ck * v2.y;                               \
      a[6] += ck * v3.x; a[7] += ck * v3.y; }

#define QUAD_LADDER(CNT)                                                  \
    { int k = 0;                                                          \
      for (; k + 16 <= (CNT); k += 16) {                                  \
          QUAD_LOAD(0) QUAD_LOAD(4) QUAD_LOAD(8) QUAD_LOAD(12)            \
      }                                                                   \
      if (k + 8 <= (CNT)) { QUAD_LOAD(0) QUAD_LOAD(4) k += 8; }           \
      if (k + 4 <= (CNT)) { QUAD_LOAD(0) k += 4; }                        \
      if (k < (CNT)) QUAD_LOAD(0) }

__global__ void k_agg(int n, int layer) {
    __shared__ float s_sum[DIM];
    __shared__ float s_sq [DIM];
    int t = threadIdx.x;
    int lane = t & 31;
    int wid = t >> 5;
    int q  = lane >> 3;
    int ql = lane & 7;
    if (t < DIM) { s_sum[t] = 0.f; s_sq[t] = 0.f; }
    __syncthreads();

    const uint4* fpH = (const uint4*)g_featH;
    float bn1[8], bn2[8];
    #pragma unroll
    for (int j = 0; j < 8; j++) { bn1[j] = 0.f; bn2[j] = 0.f; }

    int d_base = blockIdx.x * 64 + wid * 8;
    int idx = d_base + lane; if (idx > n) idx = n;
    int rp = (lane < 9) ? g_rowptr[idx] : 0;
    float erv = (lane < 8 && d_base + lane < n) ? g_er[d_base + lane] : 0.f;

    // prefetch dst 0's first chunk (srcsorted + el)
    int sP = 0; float elP = 0.f;
    if (d_base < n) {
        int rs0 = __shfl_sync(FULLM, rp, 0);
        int re0 = __shfl_sync(FULLM, rp, 1);
        int c0 = re0 - rs0; if (c0 > 32) c0 = 32;
        if (lane < c0) {
            sP = g_srcsorted[rs0 + lane];
            elP = g_el[sP];
        }
    }

    #pragma unroll 1
    for (int i = 0; i < 8; i++) {
        int d = d_base + i;
        if (d >= n) break;
        int rsC = __shfl_sync(FULLM, rp, i);
        int reC = __shfl_sync(FULLM, rp, i + 1);
        int cnt = reC - rsC; if (cnt > 32) cnt = 32;
        float er_d = __shfl_sync(FULLM, erv, i);

        // attention for current dst from prefetched operands
        int s = sP;
        float x = elP + er_d;
        x = x > 0.f ? x : NEG_SLOPE * x;
        float ex = (lane < cnt) ? __expf(x) : 0.f;
        float sum = ex;

        // issue next dst's loads NOW (hidden behind the quads below)
        sP = 0; elP = 0.f;
        if (i < 7 && d + 1 < n) {
            int rsN = reC;
            int reN = __shfl_sync(FULLM, rp, i + 2);
            int cntN = reN - rsN; if (cntN > 32) cntN = 32;
            if (lane < cntN) {
                sP = g_srcsorted[rsN + lane];
                elP = g_el[sP];
            }
        }

        float a[8];
        #pragma unroll
        for (int j = 0; j < 8; j++) a[j] = 0.f;

        // chunk 0 quads (uses s/ex)
        QUAD_LADDER(cnt)

        // extra chunks (degree > 32), serial fallback
        for (int base = rsC + 32; base < reC; base += 32) {
            int cnt2 = reC - base; if (cnt2 > 32) cnt2 = 32;
            int s2 = 0; float ex2 = 0.f;
            if (lane < cnt2) {
                s2 = g_srcsorted[base + lane];
                float x2 = g_el[s2] + er_d;
                x2 = x2 > 0.f ? x2 : NEG_SLOPE * x2;
                ex2 = __expf(x2);
            }
            sum += ex2;
            {
                int s = s2; float ex = ex2;
                QUAD_LADDER(cnt2)
            }
        }

        // softmax denominator (after quads — off the critical path)
        #pragma unroll
        for (int off = 16; off > 0; off >>= 1)
            sum += __shfl_xor_sync(FULLM, sum, off);
        float inv = sum > 0.f ? 1.f / sum : 0.f;

        #pragma unroll
        for (int j = 0; j < 8; j++) {
            a[j] += __shfl_xor_sync(FULLM, a[j], 8);
            a[j] += __shfl_xor_sync(FULLM, a[j], 16);
            a[j] *= inv;
        }

        if (q == 0) {
            float4 lo = make_float4(a[0], a[1], a[2], a[3]);
            float4 hi = make_float4(a[4], a[5], a[6], a[7]);
            ((float4*)g_acc)[(size_t)d * 16 + ql * 2 + 0] = lo;
            ((float4*)g_acc)[(size_t)d * 16 + ql * 2 + 1] = hi;
            #pragma unroll
            for (int j = 0; j < 8; j++) {
                bn1[j] += a[j];
                bn2[j] += a[j] * a[j];
            }
        }
    }

    if (q == 0) {
        #pragma unroll
        for (int j = 0; j < 8; j++) {
            atomicAdd(&s_sum[ql * 8 + j], bn1[j]);
            atomicAdd(&s_sq [ql * 8 + j], bn2[j]);
        }
    }
    __syncthreads();
    if (t < DIM) {
        atomicAdd(&g_bnsum2[layer][t], (double)s_sum[t]);
        atomicAdd(&g_bnsq2 [layer][t], (double)s_sq [t]);
    }
}

// ---------------- K3: final BN apply -------------------------------------
__global__ void k_bnapply(float* __restrict__ out,
                          const float* __restrict__ gma,
                          const float* __restrict__ beta,
                          int n, int total4) {
    __shared__ float scs[DIM], shs[DIM];
    int t = threadIdx.x;
    if (t < DIM) {
        double inv_n = 1.0 / (double)n;
        double mu  = g_bnsum2[2][t] * inv_n;
        double var = g_bnsq2[2][t] * inv_n - mu * mu;
        float rs = rsqrtf((float)var + BN_EPS);
        float sc = rs * gma[t];
        scs[t] = sc;
        shs[t] = beta[t] - (float)mu * sc;
    }
    __syncthreads();
    int idx4 = blockIdx.x * blockDim.x + t;
    if (idx4 >= total4) return;
    int c = (idx4 & 15) * 4;
    float4 a = ((const float4*)g_acc)[idx4];
    float4 v;
    v.x = a.x * scs[c + 0] + shs[c + 0];
    v.y = a.y * scs[c + 1] + shs[c + 1];
    v.z = a.z * scs[c + 2] + shs[c + 2];
    v.w = a.w * scs[c + 3] + shs[c + 3];
    ((float4*)out)[idx4] = v;
}

// ---------------- host ---------------------------------------------------
extern "C" void kernel_launch(void* const* d_in, const int* in_sizes, int n_in,
                              void* d_out, int out_size) {
    const float* node_w = (const float*)d_in[0];
    const int*   src    = (const int*)d_in[2];
    const int*   dst    = (const int*)d_in[3];
    int n = in_sizes[0] / DIM;
    int E = in_sizes[2];
    float* out = (float*)d_out;

    // Fork: CSR build on side stream, layer-0 GEMM on main stream.
    cudaEventRecord(g_aux.e0, 0);
    cudaStreamWaitEvent(g_aux.s2, g_aux.e0, 0);

    int nb = (n + SCAN_BS - 1) / SCAN_BS;
    k_hist  <<<(E + 255) / 256, 256, 0, g_aux.s2>>>(dst, E);
    k_scan1 <<<nb, SCAN_BS, 0, g_aux.s2>>>(n);
    k_scan23<<<(n + 256) / 256, 256, 0, g_aux.s2>>>(nb, n);
    k_place <<<(E + 255) / 256, 256, 0, g_aux.s2>>>(src, dst, E);
    cudaEventRecord(g_aux.e1, g_aux.s2);

    for (int layer = 0; layer < 3; layer++) {
        const float* W    = (const float*)d_in[4 + layer * 6 + 0];
        const float* al   = (const float*)d_in[4 + layer * 6 + 1];
        const float* ar   = (const float*)d_in[4 + layer * 6 + 2];
        const float* gmaP  = layer > 0 ? (const float*)d_in[4 + (layer - 1) * 6 + 4] : nullptr;
        const float* betaP = layer > 0 ? (const float*)d_in[4 + (layer - 1) * 6 + 5] : nullptr;

        k_gemm<<<(n + 63) / 64, 256>>>(layer == 0 ? node_w : nullptr,
                                       layer, W, al, ar, gmaP, betaP, n);
        if (layer == 0) cudaStreamWaitEvent(0, g_aux.e1, 0);  // CSR ready
        k_agg<<<(n + 63) / 64, 256>>>(n, layer);
    }
    const float* gma3  = (const float*)d_in[4 + 2 * 6 + 4];
    const float* beta3 = (const float*)d_in[4 + 2 * 6 + 5];
    int total4 = n * DIM / 4;
    k_bnapply<<<(total4 + 255) / 256, 256>>>(out, gma3, beta3, n, total4);
}

// round 15
// speedup vs baseline: 1.1161x; 1.0259x over previous
#include <cuda_runtime.h>
#include <cuda_bf16.h>
#include <cuda_fp16.h>

#define NNODES 100000
#define NEDGES 1600000
#define DIM 64
#define NEG_SLOPE 0.2f
#define BN_EPS 1e-5f
#define SCAN_BS 1024
#define FULLM 0xffffffffu

// Packed dual-fp32 FMA (sm_103a FFMA2) — PTX-only, full fp32 precision.
#define FMA2(D, A, B, C) \
    asm("fma.rn.f32x2 %0, %1, %2, %3;" : "=l"(D) : "l"(A), "l"(B), "l"(C))
#define PACKF2(D, LO, HI) \
    asm("mov.b64 %0, {%1, %2};" : "=l"(D) : "f"(LO), "f"(HI))
#define UNPACKF2(LO, HI, S) \
    asm("mov.b64 {%0, %1}, %2;" : "=f"(LO), "=f"(HI) : "l"(S))

// ---------------- scratch -----------------------------------------------
__device__ __half g_featH[NNODES * DIM];  // projected features, fp16 rows (128B)
__device__ float  g_acc [NNODES * DIM];   // layer output (pre-BN), fp32
__device__ float  g_el  [NNODES];
__device__ float  g_er  [NNODES];
__device__ int    g_deg [NNODES];         // zero-init; self-restored each run
__device__ int    g_rowptr[NNODES + 1];
__device__ int    g_off [NNODES];
__device__ int    g_srcsorted[NEDGES];
__device__ int    g_bsum[256];
__device__ double g_bnsum2[3][DIM];
__device__ double g_bnsq2 [3][DIM];

// Side stream + events (created pre-main, no device memory).
struct AuxStreams {
    cudaStream_t s2;
    cudaEvent_t  e0, e1;
    AuxStreams() {
        cudaStreamCreateWithFlags(&s2, cudaStreamNonBlocking);
        cudaEventCreateWithFlags(&e0, cudaEventDisableTiming);
        cudaEventCreateWithFlags(&e1, cudaEventDisableTiming);
    }
};
static AuxStreams g_aux;

// ---------------- CSR build ----------------------------------------------
__global__ void k_hist(const int* __restrict__ dst, int E) {
    int e = blockIdx.x * blockDim.x + threadIdx.x;
    if (e < E) atomicAdd(&g_deg[dst[e]], 1);
}
// scan1 re-zeroes g_deg after reading (zero at static init for run 1).
__global__ void k_scan1(int n) {
    __shared__ int wsum[32];
    int t = threadIdx.x, lane = t & 31, w = t >> 5;
    int idx = blockIdx.x * SCAN_BS + t;
    int val = (idx < n) ? g_deg[idx] : 0;
    if (idx < n) g_deg[idx] = 0;
    int x = val;
    #pragma unroll
    for (int off = 1; off < 32; off <<= 1) {
        int y = __shfl_up_sync(FULLM, x, off);
        if (lane >= off) x += y;
    }
    if (lane == 31) wsum[w] = x;
    __syncthreads();
    if (w == 0) {
        int y = wsum[lane];
        int z = y;
        #pragma unroll
        for (int off = 1; off < 32; off <<= 1) {
            int u = __shfl_up_sync(FULLM, z, off);
            if (lane >= off) z += u;
        }
        wsum[lane] = z - y;
    }
    __syncthreads();
    int incl = x + wsum[w];
    if (idx < n) g_rowptr[idx] = incl - val;
    if (t == SCAN_BS - 1) g_bsum[blockIdx.x] = incl;
}
// scan2+scan3 merged: every block scans the <=128 block sums in parallel,
// then applies the offset to its slice of rowptr.
__global__ void k_scan23(int nb, int n) {
    __shared__ int sboff[130];
    __shared__ int wsum[4];
    int t = threadIdx.x;
    int lane = t & 31, w = t >> 5;
    int x = 0, val = 0;
    if (t < 128) {
        val = (t < nb) ? g_bsum[t] : 0;
        x = val;
        #pragma unroll
        for (int off = 1; off < 32; off <<= 1) {
            int y = __shfl_up_sync(FULLM, x, off);
            if (lane >= off) x += y;
        }
        if (lane == 31) wsum[w] = x;
    }
    __syncthreads();
    if (t < 128) {
        int add = 0;
        #pragma unroll
        for (int i = 0; i < 4; i++) if (i < w) add += wsum[i];
        int incl = x + add;
        if (t < nb) sboff[t] = incl - val;       // exclusive prefix
        if (t == nb - 1) sboff[nb] = incl;       // total = E
    }
    __syncthreads();
    int i = blockIdx.x * blockDim.x + t;
    if (i < n) {
        int v = g_rowptr[i] + sboff[i / SCAN_BS];
        g_rowptr[i] = v;
        g_off[i] = v;
    }
    if (i == n) g_rowptr[n] = sboff[nb];
}
// place also zeroes the BN stat slots (block 0) — strictly before any k_agg.
__global__ void k_place(const int* __restrict__ src,
                        const int* __restrict__ dst, int E) {
    if (blockIdx.x == 0 && threadIdx.x < 192) {
        ((double*)g_bnsum2)[threadIdx.x] = 0.0;
        ((double*)g_bnsq2)[threadIdx.x] = 0.0;
    }
    int e = blockIdx.x * blockDim.x + threadIdx.x;
    if (e < E) {
        int pos = atomicAdd(&g_off[dst[e]], 1);
        g_srcsorted[pos] = src[e];
    }
}

// ---------------- K1: feat = h @ W via packed f32x2 FMA ------------------
// PDL: stages W/al/ar (pure inputs) BEFORE cudaGridDependencySynchronize();
// touches g_acc / BN stats (predecessor k_agg's output) only after.
__global__ void k_gemm(const float* __restrict__ hin_ext, int layer,
                       const float* __restrict__ W,
                       const float* __restrict__ al,
                       const float* __restrict__ ar,
                       const float* __restrict__ gmaP,
                       const float* __restrict__ betaP,
                       int n) {
    __shared__ float Ws[DIM * DIM];
    __shared__ float hs[64 * DIM];
    __shared__ float als[DIM], ars[DIM], scs[DIM], shs[DIM];

    int t = threadIdx.x;
    int row0 = blockIdx.x * 64;

    // pre-sync prologue: inputs only
    for (int i = t; i < DIM * DIM / 4; i += 256)
        ((float4*)Ws)[i] = ((const float4*)W)[i];
    if (t < DIM) { als[t] = al[t]; ars[t] = ar[t]; }

    cudaGridDependencySynchronize();   // wait for predecessor (k_agg) output

    if (layer > 0 && t < DIM) {
        double inv_n = 1.0 / (double)n;
        double mu  = g_bnsum2[layer - 1][t] * inv_n;
        double var = g_bnsq2[layer - 1][t] * inv_n - mu * mu;
        float rs = rsqrtf((float)var + BN_EPS);
        float sc = rs * gmaP[t];
        scs[t] = sc;
        shs[t] = betaP[t] - (float)mu * sc;
    }
    __syncthreads();

    int nrows = n - row0; if (nrows > 64) nrows = 64;
    if (layer > 0) {
        for (int i = t; i < nrows * (DIM / 4); i += 256) {
            float4 a = ((const float4*)(g_acc + (size_t)row0 * DIM))[i];
            int c = (i & 15) * 4;
            float4 v;
            v.x = a.x * scs[c + 0] + shs[c + 0];
            v.y = a.y * scs[c + 1] + shs[c + 1];
            v.z = a.z * scs[c + 2] + shs[c + 2];
            v.w = a.w * scs[c + 3] + shs[c + 3];
            v.x = v.x > 0.f ? v.x : (__expf(v.x) - 1.f);
            v.y = v.y > 0.f ? v.y : (__expf(v.y) - 1.f);
            v.z = v.z > 0.f ? v.z : (__expf(v.z) - 1.f);
            v.w = v.w > 0.f ? v.w : (__expf(v.w) - 1.f);
            ((float4*)hs)[i] = v;
        }
    } else {
        for (int i = t; i < nrows * (DIM / 4); i += 256)
            ((float4*)hs)[i] = ((const float4*)(hin_ext + (size_t)row0 * DIM))[i];
    }
    __syncthreads();

    int cg = t & 15, rg = t >> 4;
    int r0 = rg * 4;

    unsigned long long accP[2][4];
    #pragma unroll
    for (int rp = 0; rp < 2; rp++)
        #pragma unroll
        for (int c = 0; c < 4; c++) accP[rp][c] = 0ULL;

    const float4* Ws4 = (const float4*)Ws;
    #pragma unroll
    for (int k = 0; k < DIM; k += 4) {
        float4 wv[4];
        wv[0] = Ws4[(k + 0) * 16 + cg];
        wv[1] = Ws4[(k + 1) * 16 + cg];
        wv[2] = Ws4[(k + 2) * 16 + cg];
        wv[3] = Ws4[(k + 3) * 16 + cg];
        float4 hA = *(const float4*)(hs + (r0 + 0) * DIM + k);
        float4 hB = *(const float4*)(hs + (r0 + 1) * DIM + k);
        float4 hC = *(const float4*)(hs + (r0 + 2) * DIM + k);
        float4 hD = *(const float4*)(hs + (r0 + 3) * DIM + k);
        const float* pA = &hA.x; const float* pB = &hB.x;
        const float* pC = &hC.x; const float* pD = &hD.x;
        #pragma unroll
        for (int kk = 0; kk < 4; kk++) {
            unsigned long long h01, h23, wxx, wyy, wzz, www;
            PACKF2(h01, pA[kk], pB[kk]);
            PACKF2(h23, pC[kk], pD[kk]);
            PACKF2(wxx, wv[kk].x, wv[kk].x);
            PACKF2(wyy, wv[kk].y, wv[kk].y);
            PACKF2(wzz, wv[kk].z, wv[kk].z);
            PACKF2(www, wv[kk].w, wv[kk].w);
            FMA2(accP[0][0], h01, wxx, accP[0][0]);
            FMA2(accP[0][1], h01, wyy, accP[0][1]);
            FMA2(accP[0][2], h01, wzz, accP[0][2]);
            FMA2(accP[0][3], h01, www, accP[0][3]);
            FMA2(accP[1][0], h23, wxx, accP[1][0]);
            FMA2(accP[1][1], h23, wyy, accP[1][1]);
            FMA2(accP[1][2], h23, wzz, accP[1][2]);
            FMA2(accP[1][3], h23, www, accP[1][3]);
        }
    }

    float accf[4][4];
    #pragma unroll
    for (int rp = 0; rp < 2; rp++)
        #pragma unroll
        for (int c = 0; c < 4; c++)
            UNPACKF2(accf[2 * rp][c], accf[2 * rp + 1][c], accP[rp][c]);

    float4 alv = ((float4*)als)[cg];
    float4 arv = ((float4*)ars)[cg];
    #pragma unroll
    for (int r = 0; r < 4; r++) {
        int row = row0 + r0 + r;
        float ax = accf[r][0], ay = accf[r][1], az = accf[r][2], aw = accf[r][3];
        float pl = ax * alv.x + ay * alv.y + az * alv.z + aw * alv.w;
        float pr = ax * arv.x + ay * arv.y + az * arv.z + aw * arv.w;
        #pragma unroll
        for (int off = 8; off > 0; off >>= 1) {
            pl += __shfl_xor_sync(FULLM, pl, off);
            pr += __shfl_xor_sync(FULLM, pr, off);
        }
        if (row < n) {
            __half2 h01 = __floats2half2_rn(ax, ay);
            __half2 h23 = __floats2half2_rn(az, aw);
            uint2 u;
            u.x = *(unsigned int*)&h01;
            u.y = *(unsigned int*)&h23;
            *(uint2*)(g_featH + (size_t)row * DIM + cg * 4) = u;
            if (cg == 0) { g_el[row] = pl; g_er[row] = pr; }
        }
    }
}

// ---------------- K2: fused softmax + aggregation + BN stats -------------
// PDL: pre-sync prologue = smem zero + rowptr load (CSR complete at launch);
// syncs before touching g_er/g_el/g_featH (predecessor k_gemm's output).
// Triggers the dependent launch before the BN-atomic epilogue.
#define QUAD_LOAD(KOFF)                                                   \
    { int   sk = __shfl_sync(FULLM, s,  k + (KOFF) + q);                  \
      float ck = __shfl_sync(FULLM, ex, k + (KOFF) + q);                  \
      uint4 f = fpH[(size_t)sk * 8 + ql];                                 \
      float2 v0 = __half22float2(*(__half2*)&f.x);                        \
      float2 v1 = __half22float2(*(__half2*)&f.y);                        \
      float2 v2 = __half22float2(*(__half2*)&f.z);                        \
      float2 v3 = __half22float2(*(__half2*)&f.w);                        \
      a[0] += ck * v0.x; a[1] += ck * v0.y;                               \
      a[2] += ck * v1.x; a[3] += ck * v1.y;                               \
      a[4] += ck * v2.x; a[5] += ck * v2.y;                               \
      a[6] += ck * v3.x; a[7] += ck * v3.y; }

#define QUAD_LADDER(CNT)                                                  \
    { int k = 0;                                                          \
      for (; k + 16 <= (CNT); k += 16) {                                  \
          QUAD_LOAD(0) QUAD_LOAD(4) QUAD_LOAD(8) QUAD_LOAD(12)            \
      }                                                                   \
      if (k + 8 <= (CNT)) { QUAD_LOAD(0) QUAD_LOAD(4) k += 8; }           \
      if (k + 4 <= (CNT)) { QUAD_LOAD(0) k += 4; }                        \
      if (k < (CNT)) QUAD_LOAD(0) }

__global__ void k_agg(int n, int layer) {
    __shared__ float s_sum[DIM];
    __shared__ float s_sq [DIM];
    int t = threadIdx.x;
    int lane = t & 31;
    int wid = t >> 5;
    int q  = lane >> 3;
    int ql = lane & 7;
    if (t < DIM) { s_sum[t] = 0.f; s_sq[t] = 0.f; }

    int d_base = blockIdx.x * 64 + wid * 8;
    int idx = d_base + lane; if (idx > n) idx = n;
    int rp = (lane < 9) ? g_rowptr[idx] : 0;   // CSR: complete at launch

    cudaGridDependencySynchronize();   // wait for k_gemm's featH/el/er
    __syncthreads();

    const uint4* fpH = (const uint4*)g_featH;
    float bn1[8], bn2[8];
    #pragma unroll
    for (int j = 0; j < 8; j++) { bn1[j] = 0.f; bn2[j] = 0.f; }

    float erv = (lane < 8 && d_base + lane < n) ? g_er[d_base + lane] : 0.f;

    // prefetch dst 0's first chunk (srcsorted + el)
    int sP = 0; float elP = 0.f;
    if (d_base < n) {
        int rs0 = __shfl_sync(FULLM, rp, 0);
        int re0 = __shfl_sync(FULLM, rp, 1);
        int c0 = re0 - rs0; if (c0 > 32) c0 = 32;
        if (lane < c0) {
            sP = g_srcsorted[rs0 + lane];
            elP = g_el[sP];
        }
    }

    #pragma unroll 1
    for (int i = 0; i < 8; i++) {
        int d = d_base + i;
        if (d >= n) break;
        int rsC = __shfl_sync(FULLM, rp, i);
        int reC = __shfl_sync(FULLM, rp, i + 1);
        int cnt = reC - rsC; if (cnt > 32) cnt = 32;
        float er_d = __shfl_sync(FULLM, erv, i);

        // attention for current dst from prefetched operands
        int s = sP;
        float x = elP + er_d;
        x = x > 0.f ? x : NEG_SLOPE * x;
        float ex = (lane < cnt) ? __expf(x) : 0.f;
        float sum = ex;

        // issue next dst's loads NOW (hidden behind the quads below)
        sP = 0; elP = 0.f;
        if (i < 7 && d + 1 < n) {
            int rsN = reC;
            int reN = __shfl_sync(FULLM, rp, i + 2);
            int cntN = reN - rsN; if (cntN > 32) cntN = 32;
            if (lane < cntN) {
                sP = g_srcsorted[rsN + lane];
                elP = g_el[sP];
            }
        }

        float a[8];
        #pragma unroll
        for (int j = 0; j < 8; j++) a[j] = 0.f;

        // chunk 0 quads (uses s/ex)
        QUAD_LADDER(cnt)

        // extra chunks (degree > 32), serial fallback
        for (int base = rsC + 32; base < reC; base += 32) {
            int cnt2 = reC - base; if (cnt2 > 32) cnt2 = 32;
            int s2 = 0; float ex2 = 0.f;
            if (lane < cnt2) {
                s2 = g_srcsorted[base + lane];
                float x2 = g_el[s2] + er_d;
                x2 = x2 > 0.f ? x2 : NEG_SLOPE * x2;
                ex2 = __expf(x2);
            }
            sum += ex2;
            {
                int s = s2; float ex = ex2;
                QUAD_LADDER(cnt2)
            }
        }

        // softmax denominator (after quads — off the critical path)
        #pragma unroll
        for (int off = 16; off > 0; off >>= 1)
            sum += __shfl_xor_sync(FULLM, sum, off);
        float inv = sum > 0.f ? 1.f / sum : 0.f;

        #pragma unroll
        for (int j = 0; j < 8; j++) {
            a[j] += __shfl_xor_sync(FULLM, a[j], 8);
            a[j] += __shfl_xor_sync(FULLM, a[j], 16);
            a[j] *= inv;
        }

        if (q == 0) {
            float4 lo = make_float4(a[0], a[1], a[2], a[3]);
            float4 hi = make_float4(a[4], a[5], a[6], a[7]);
            ((float4*)g_acc)[(size_t)d * 16 + ql * 2 + 0] = lo;
            ((float4*)g_acc)[(size_t)d * 16 + ql * 2 + 1] = hi;
            #pragma unroll
            for (int j = 0; j < 8; j++) {
                bn1[j] += a[j];
                bn2[j] += a[j] * a[j];
            }
        }
    }

    // allow the dependent kernel to start staging during our atomic tail
    cudaTriggerProgrammaticLaunchCompletion();

    if (q == 0) {
        #pragma unroll
        for (int j = 0; j < 8; j++) {
            atomicAdd(&s_sum[ql * 8 + j], bn1[j]);
            atomicAdd(&s_sq [ql * 8 + j], bn2[j]);
        }
    }
    __syncthreads();
    if (t < DIM) {
        atomicAdd(&g_bnsum2[layer][t], (double)s_sum[t]);
        atomicAdd(&g_bnsq2 [layer][t], (double)s_sq [t]);
    }
}

// ---------------- K3: final BN apply -------------------------------------
__global__ void k_bnapply(float* __restrict__ out,
                          const float* __restrict__ gma,
                          const float* __restrict__ beta,
                          int n, int total4) {
    __shared__ float scs[DIM], shs[DIM];
    int t = threadIdx.x;
    cudaGridDependencySynchronize();
    if (t < DIM) {
        double inv_n = 1.0 / (double)n;
        double mu  = g_bnsum2[2][t] * inv_n;
        double var = g_bnsq2[2][t] * inv_n - mu * mu;
        float rs = rsqrtf((float)var + BN_EPS);
        float sc = rs * gma[t];
        scs[t] = sc;
        shs[t] = beta[t] - (float)mu * sc;
    }
    __syncthreads();
    int idx4 = blockIdx.x * blockDim.x + t;
    if (idx4 >= total4) return;
    int c = (idx4 & 15) * 4;
    float4 a = ((const float4*)g_acc)[idx4];
    float4 v;
    v.x = a.x * scs[c + 0] + shs[c + 0];
    v.y = a.y * scs[c + 1] + shs[c + 1];
    v.z = a.z * scs[c + 2] + shs[c + 2];
    v.w = a.w * scs[c + 3] + shs[c + 3];
    ((float4*)out)[idx4] = v;
}

// ---------------- host ---------------------------------------------------
extern "C" void kernel_launch(void* const* d_in, const int* in_sizes, int n_in,
                              void* d_out, int out_size) {
    const float* node_w = (const float*)d_in[0];
    const int*   src    = (const int*)d_in[2];
    const int*   dst    = (const int*)d_in[3];
    int n = in_sizes[0] / DIM;
    int E = in_sizes[2];
    float* out = (float*)d_out;

    // Fork: CSR build on side stream, layer-0 GEMM on main stream.
    cudaEventRecord(g_aux.e0, 0);
    cudaStreamWaitEvent(g_aux.s2, g_aux.e0, 0);

    int nb = (n + SCAN_BS - 1) / SCAN_BS;
    k_hist  <<<(E + 255) / 256, 256, 0, g_aux.s2>>>(dst, E);
    k_scan1 <<<nb, SCAN_BS, 0, g_aux.s2>>>(n);
    k_scan23<<<(n + 256) / 256, 256, 0, g_aux.s2>>>(nb, n);
    k_place <<<(E + 255) / 256, 256, 0, g_aux.s2>>>(src, dst, E);
    cudaEventRecord(g_aux.e1, g_aux.s2);

    // PDL launch config (main stream)
    cudaLaunchAttribute pdlAttr;
    pdlAttr.id = cudaLaunchAttributeProgrammaticStreamSerialization;
    pdlAttr.val.programmaticStreamSerializationAllowed = 1;

    int gemm_grid = (n + 63) / 64;
    int agg_grid  = (n + 63) / 64;

    for (int layer = 0; layer < 3; layer++) {
        const float* W    = (const float*)d_in[4 + layer * 6 + 0];
        const float* al   = (const float*)d_in[4 + layer * 6 + 1];
        const float* ar   = (const float*)d_in[4 + layer * 6 + 2];
        const float* gmaP  = layer > 0 ? (const float*)d_in[4 + (layer - 1) * 6 + 4] : nullptr;
        const float* betaP = layer > 0 ? (const float*)d_in[4 + (layer - 1) * 6 + 5] : nullptr;
        const float* hin   = layer == 0 ? node_w : nullptr;

        if (layer == 0) {
            k_gemm<<<gemm_grid, 256>>>(hin, layer, W, al, ar, gmaP, betaP, n);
            cudaStreamWaitEvent(0, g_aux.e1, 0);  // CSR ready before agg0
            k_agg<<<agg_grid, 256>>>(n, layer);   // plain launch (event edge)
        } else {
            cudaLaunchConfig_t cfg = {};
            cfg.gridDim = dim3(gemm_grid, 1, 1);
            cfg.blockDim = dim3(256, 1, 1);
            cfg.dynamicSmemBytes = 0;
            cfg.stream = 0;
            cfg.attrs = &pdlAttr;
            cfg.numAttrs = 1;
            cudaLaunchKernelEx(&cfg, k_gemm, hin, layer, W, al, ar, gmaP, betaP, n);

            cudaLaunchConfig_t cfg2 = {};
            cfg2.gridDim = dim3(agg_grid, 1, 1);
            cfg2.blockDim = dim3(256, 1, 1);
            cfg2.dynamicSmemBytes = 0;
            cfg2.stream = 0;
            cfg2.attrs = &pdlAttr;
            cfg2.numAttrs = 1;
            cudaLaunchKernelEx(&cfg2, k_agg, n, layer);
        }
    }
    const float* gma3  = (const float*)d_in[4 + 2 * 6 + 4];
    const float* beta3 = (const float*)d_in[4 + 2 * 6 + 5];
    int total4 = n * DIM / 4;
    cudaLaunchConfig_t cfg3 = {};
    cfg3.gridDim = dim3((total4 + 255) / 256, 1, 1);
    cfg3.blockDim = dim3(256, 1, 1);
    cfg3.dynamicSmemBytes = 0;
    cfg3.stream = 0;
    cfg3.attrs = &pdlAttr;
    cfg3.numAttrs = 1;
    cudaLaunchKernelEx(&cfg3, k_bnapply, out, gma3, beta3, n, total4);
}